// round 14
// baseline (speedup 1.0000x reference)
#include <cuda_runtime.h>
#include <cuda_bf16.h>
#include <math.h>
#include <cstdint>

#define NN 1024
#define MV 32

// Scratch (allocation-free: __device__ globals)
__device__ float g_h[NN * MV];
__device__ float g_Ai[NN * MV];
__device__ float g_Bj[NN * MV];
__device__ float g_msum[NN * MV];

// ---------------- warp-MMA helpers (baseline PTX, sm_80+) ------------------
__device__ __forceinline__ uint32_t smem_u32(const void* p)
{
    uint32_t a;
    asm("{ .reg .u64 t; cvta.to.shared.u64 t, %1; cvt.u32.u64 %0, t; }"
        : "=r"(a) : "l"(p));
    return a;
}
__device__ __forceinline__ void ldm_x4(uint32_t* r, uint32_t addr)
{
    asm volatile("ldmatrix.sync.aligned.m8n8.x4.shared.b16 {%0,%1,%2,%3}, [%4];"
                 : "=r"(r[0]), "=r"(r[1]), "=r"(r[2]), "=r"(r[3]) : "r"(addr));
}
__device__ __forceinline__ void mma16816(float* d, const uint32_t* a,
                                         uint32_t b0, uint32_t b1)
{
    asm volatile("mma.sync.aligned.m16n8k16.row.col.f32.bf16.bf16.f32 "
                 "{%0,%1,%2,%3}, {%4,%5,%6,%7}, {%8,%9}, {%0,%1,%2,%3};"
                 : "+f"(d[0]), "+f"(d[1]), "+f"(d[2]), "+f"(d[3])
                 : "r"(a[0]), "r"(a[1]), "r"(a[2]), "r"(a[3]), "r"(b0), "r"(b1));
}
__device__ __forceinline__ uint32_t pack_bf(float a, float b)
{
    __nv_bfloat162 t;
    t.x = __float2bfloat16_rn(a);
    t.y = __float2bfloat16_rn(b);
    return *reinterpret_cast<uint32_t*>(&t);
}
__device__ __forceinline__ uint32_t pack_hi(float a, float b, float& ra, float& rb)
{
    __nv_bfloat162 t;
    t.x = __float2bfloat16_rn(a);
    t.y = __float2bfloat16_rn(b);
    ra = a - __bfloat162float(t.x);
    rb = b - __bfloat162float(t.y);
    return *reinterpret_cast<uint32_t*>(&t);
}

// ---------------------------------------------------------------------------
// init: h=0, msum=0, Ai = b[i]*wbi + b1, Bj = b[i]*wbj  (closed form at h=0)
// ---------------------------------------------------------------------------
__global__ __launch_bounds__(256, 1)
void init_kernel(const float* __restrict__ W1,
                 const float* __restrict__ b,
                 const float* __restrict__ b1)
{
    const int idx = blockIdx.x * 256 + threadIdx.x;     // 0..32767
    const int i = idx >> 5, m = idx & 31;
    const float bi = b[i];
    g_h[idx] = 0.f;
    g_msum[idx] = 0.f;
    g_Ai[idx] = bi * W1[m * 67 + 65] + b1[m];
    g_Bj[idx] = bi * W1[m * 67 + 66];
}

// ---------------------------------------------------------------------------
// Edge MLP via mma.sync bf16 hi/lo 3-product split (~fp32 accuracy).
// Grid (32 j-tiles, 16 i-chunks of 64), block 128 (4 warps), 32 iterations.
// Warp w owns rows w*16..w*16+15 for build/ldmatrix/epilogue -> __syncwarp only.
// ---------------------------------------------------------------------------
__global__ __launch_bounds__(128)
void edge_kernel(const float* __restrict__ Jm,
                 const float* __restrict__ W1,
                 const float* __restrict__ W2,
                 const float* __restrict__ W3,
                 const float* __restrict__ b2,
                 const float* __restrict__ b3)
{
    __shared__ float j_s[2048];                   // [il][j]  il in 0..63
    __shared__ float ai_s[2048];                  // [il][k]
    __shared__ float bj_s[32 * 33];               // [k][j] padded
    __shared__ float wj_s[32];
    __shared__ float b2_s[32], b3_s[32];
    __shared__ alignas(8) uint32_t wfrag[2048];   // B-frags: [plane][kt][nt][lane]{b0,b1}
    __shared__ __nv_bfloat16 xs0[64 * 40];        // activation hi plane (stride 40)
    __shared__ __nv_bfloat16 xs1[64 * 40];        // activation lo plane
    __shared__ float red_s[32 * 33];

    const int tid = threadIdx.x;
    const int lane = tid & 31, w = tid >> 5;
    const int j0 = blockIdx.x * 32, i0 = blockIdx.y * 64;

    // ---- stage J (64x32), Ai (64x32), Bj(kxj), wj, biases ----
    for (int idx = tid; idx < 2048; idx += 128) {
        j_s[idx] = Jm[(size_t)(i0 + (idx >> 5)) * NN + j0 + (idx & 31)];
        ai_s[idx] = g_Ai[(i0 + (idx >> 5)) * 32 + (idx & 31)];
    }
    for (int idx = tid; idx < 1024; idx += 128)
        bj_s[(idx & 31) * 33 + (idx >> 5)] = g_Bj[(j0 + (idx >> 5)) * 32 + (idx & 31)];
    if (tid < 32) { wj_s[tid] = W1[tid * 67 + 64]; b2_s[tid] = b2[tid]; b3_s[tid] = b3[tid]; }

    // ---- precompute per-lane B fragments: planes 0=W2hi 1=W2lo 2=W3hi 3=W3lo
    for (int e = tid; e < 1024; e += 128) {
        const int ln = e & 31, q = e >> 5, nt = q & 3, q2 = q >> 2;
        const int kt = q2 & 1, plane = q2 >> 1;
        const int gg = ln >> 2, tt = ln & 3;
        const int n = nt * 8 + gg, k0 = kt * 16 + 2 * tt;
        const float* Wm = (plane < 2) ? W2 : W3;
        float v00 = Wm[n * 32 + k0],     v01 = Wm[n * 32 + k0 + 1];
        float v10 = Wm[n * 32 + k0 + 8], v11 = Wm[n * 32 + k0 + 9];
        if (plane & 1) {
            v00 -= __bfloat162float(__float2bfloat16_rn(v00));
            v01 -= __bfloat162float(__float2bfloat16_rn(v01));
            v10 -= __bfloat162float(__float2bfloat16_rn(v10));
            v11 -= __bfloat162float(__float2bfloat16_rn(v11));
        }
        wfrag[2 * e]     = pack_bf(v00, v01);
        wfrag[2 * e + 1] = pack_bf(v10, v11);
    }
    __syncthreads();

    // per-thread constants
    const int g = lane >> 2, t4 = lane & 3;
    float b2c[8], b3c[8];
#pragma unroll
    for (int nt = 0; nt < 4; nt++) {
        b2c[2 * nt] = b2_s[nt * 8 + 2 * t4]; b2c[2 * nt + 1] = b2_s[nt * 8 + 2 * t4 + 1];
        b3c[2 * nt] = b3_s[nt * 8 + 2 * t4]; b3c[2 * nt + 1] = b3_s[nt * 8 + 2 * t4 + 1];
    }
    const uint32_t ldmoff = (uint32_t)((w * 16 + (lane & 15)) * 80 + (lane >> 4) * 16);
    const uint32_t x0b = smem_u32(xs0) + ldmoff;
    const uint32_t x1b = smem_u32(xs1) + ldmoff;
    const int brow = tid >> 1, bkh = tid & 1;
    const int bip = brow >> 5, bj = brow & 31;
    __nv_bfloat16* xhp = xs0 + brow * 40 + bkh * 16;
    __nv_bfloat16* xlp = xs1 + brow * 40 + bkh * 16;

    float macc[16];
#pragma unroll
    for (int q = 0; q < 16; q++) macc[q] = 0.f;

#pragma unroll 1
    for (int it = 0; it < 32; it++) {
        // ---- build x1 (fp32) -> bf16 hi/lo planes (warp-own rows) ----
        const int il = it * 2 + bip;
        const float Jv = j_s[il * 32 + bj];
        const float* aip = ai_s + il * 32 + bkh * 16;
        const float* wjp = wj_s + bkh * 16;
#pragma unroll
        for (int kk = 0; kk < 16; kk += 2) {
            const int k = bkh * 16 + kk;
            float v0 = fmaxf(fmaf(Jv, wjp[kk],     aip[kk])     + bj_s[k * 33 + bj], 0.f);
            float v1 = fmaxf(fmaf(Jv, wjp[kk + 1], aip[kk + 1]) + bj_s[(k + 1) * 33 + bj], 0.f);
            float r0, r1;
            *reinterpret_cast<uint32_t*>(xhp + kk) = pack_hi(v0, v1, r0, r1);
            *reinterpret_cast<uint32_t*>(xlp + kk) = pack_bf(r0, r1);
        }
        __syncwarp();

        uint32_t ahi[8], alo[8];
        float d[16];

        // ================= layer 2 =================
        ldm_x4(ahi, x0b); ldm_x4(ahi + 4, x0b + 32);
        ldm_x4(alo, x1b); ldm_x4(alo + 4, x1b + 32);
#pragma unroll
        for (int q = 0; q < 16; q++) d[q] = 0.f;
#pragma unroll
        for (int kt = 0; kt < 2; kt++) {
#pragma unroll
            for (int nt = 0; nt < 4; nt++) {
                const uint2 bh = reinterpret_cast<const uint2*>(wfrag)[((0 + kt) * 4 + nt) * 32 + lane];
                const uint2 bl = reinterpret_cast<const uint2*>(wfrag)[((2 + kt) * 4 + nt) * 32 + lane];
                mma16816(d + 4 * nt, ahi + 4 * kt, bh.x, bh.y);
                mma16816(d + 4 * nt, alo + 4 * kt, bh.x, bh.y);
                mma16816(d + 4 * nt, ahi + 4 * kt, bl.x, bl.y);
            }
        }
        {
            const int rA = w * 16 + g, rB = rA + 8;
#pragma unroll
            for (int nt = 0; nt < 4; nt++) {
                const int c0 = nt * 8 + 2 * t4;
                float v00 = fmaxf(d[4 * nt + 0] + b2c[2 * nt],     0.f);
                float v01 = fmaxf(d[4 * nt + 1] + b2c[2 * nt + 1], 0.f);
                float v10 = fmaxf(d[4 * nt + 2] + b2c[2 * nt],     0.f);
                float v11 = fmaxf(d[4 * nt + 3] + b2c[2 * nt + 1], 0.f);
                float r00, r01, r10, r11;
                *reinterpret_cast<uint32_t*>(xs0 + rA * 40 + c0) = pack_hi(v00, v01, r00, r01);
                *reinterpret_cast<uint32_t*>(xs0 + rB * 40 + c0) = pack_hi(v10, v11, r10, r11);
                *reinterpret_cast<uint32_t*>(xs1 + rA * 40 + c0) = pack_bf(r00, r01);
                *reinterpret_cast<uint32_t*>(xs1 + rB * 40 + c0) = pack_bf(r10, r11);
            }
        }
        __syncwarp();

        // ================= layer 3 =================
        ldm_x4(ahi, x0b); ldm_x4(ahi + 4, x0b + 32);
        ldm_x4(alo, x1b); ldm_x4(alo + 4, x1b + 32);
#pragma unroll
        for (int q = 0; q < 16; q++) d[q] = 0.f;
#pragma unroll
        for (int kt = 0; kt < 2; kt++) {
#pragma unroll
            for (int nt = 0; nt < 4; nt++) {
                const uint2 bh = reinterpret_cast<const uint2*>(wfrag)[((4 + kt) * 4 + nt) * 32 + lane];
                const uint2 bl = reinterpret_cast<const uint2*>(wfrag)[((6 + kt) * 4 + nt) * 32 + lane];
                mma16816(d + 4 * nt, ahi + 4 * kt, bh.x, bh.y);
                mma16816(d + 4 * nt, alo + 4 * kt, bh.x, bh.y);
                mma16816(d + 4 * nt, ahi + 4 * kt, bl.x, bl.y);
            }
        }
#pragma unroll
        for (int nt = 0; nt < 4; nt++) {
            macc[4 * nt + 0] += fmaxf(d[4 * nt + 0] + b3c[2 * nt],     0.f);
            macc[4 * nt + 1] += fmaxf(d[4 * nt + 1] + b3c[2 * nt + 1], 0.f);
            macc[4 * nt + 2] += fmaxf(d[4 * nt + 2] + b3c[2 * nt],     0.f);
            macc[4 * nt + 3] += fmaxf(d[4 * nt + 3] + b3c[2 * nt + 1], 0.f);
        }
        __syncwarp();
    }

    // ---- reduce i-partials (warps {0,2} and {1,3} share j ranges) ----
    const int rjA = (w & 1) * 16 + g;
    if (w < 2) {
#pragma unroll
        for (int nt = 0; nt < 4; nt++) {
            const int c0 = nt * 8 + 2 * t4;
            red_s[rjA * 33 + c0]           = macc[4 * nt + 0];
            red_s[rjA * 33 + c0 + 1]       = macc[4 * nt + 1];
            red_s[(rjA + 8) * 33 + c0]     = macc[4 * nt + 2];
            red_s[(rjA + 8) * 33 + c0 + 1] = macc[4 * nt + 3];
        }
    }
    __syncthreads();
    if (w >= 2) {
#pragma unroll
        for (int nt = 0; nt < 4; nt++) {
            const int c0 = nt * 8 + 2 * t4;
            red_s[rjA * 33 + c0]           += macc[4 * nt + 0];
            red_s[rjA * 33 + c0 + 1]       += macc[4 * nt + 1];
            red_s[(rjA + 8) * 33 + c0]     += macc[4 * nt + 2];
            red_s[(rjA + 8) * 33 + c0 + 1] += macc[4 * nt + 3];
        }
    }
    __syncthreads();
    {
        const int jj = tid >> 2, mq = (tid & 3) * 8;
        float* dst = g_msum + (size_t)(j0 + jj) * 32 + mq;
#pragma unroll
        for (int q = 0; q < 8; q++) atomicAdd(dst + q, red_s[jj * 33 + mq + q]);
    }
}

// ---------------------------------------------------------------------------
// Fused GRU + next-step prep. 32 blocks x 128 threads; block owns 32 rows.
// gi = [h,msum]@Wih.T + bih; h' = (1-z)*n; then Ai/Bj from h'; msum = 0.
// ---------------------------------------------------------------------------
__global__ __launch_bounds__(128, 1)
void gruprep_kernel(const float* __restrict__ Wih,
                    const float* __restrict__ bih,
                    const float* __restrict__ bhh,
                    const float* __restrict__ W1,
                    const float* __restrict__ b,
                    const float* __restrict__ b1)
{
    __shared__ float wih_s[96 * 65];
    __shared__ float w1_s[32 * 67];
    __shared__ float inp_s[32][65];
    __shared__ float gi_s[32][97];
    __shared__ float h_s[32][33];
    __shared__ float bih_s[96], bhh_s[96], b1_s[32], b_s[32];

    const int tid = threadIdx.x;
    const int r0 = blockIdx.x * 32;
    for (int idx = tid; idx < 96 * 64; idx += 128)
        wih_s[(idx >> 6) * 65 + (idx & 63)] = Wih[idx];
    for (int idx = tid; idx < 32 * 67; idx += 128) w1_s[idx] = W1[idx];
    if (tid < 96) { bih_s[tid] = bih[tid]; bhh_s[tid] = bhh[tid]; }
    if (tid < 32) { b1_s[tid] = b1[tid]; b_s[tid] = b[r0 + tid]; }
    for (int idx = tid; idx < 2048; idx += 128) {
        const int r = idx >> 6, k = idx & 63;
        inp_s[r][k] = (k < 32) ? g_h[(r0 + r) * 32 + k]
                               : g_msum[(r0 + r) * 32 + (k - 32)];
    }
    __syncthreads();

    const int w = tid >> 5, lane = tid & 31;

    // gi: warp w owns rows w*8..w*8+7; lane computes g = lane, lane+32, lane+64
#pragma unroll 1
    for (int q = 0; q < 8; q++) {
        const int r = w * 8 + q;
#pragma unroll
        for (int p = 0; p < 3; p++) {
            const int gg = lane + 32 * p;
            const float* wr = &wih_s[gg * 65];
            float acc = bih_s[gg];
#pragma unroll
            for (int k = 0; k < 64; k++) acc = fmaf(wr[k], inp_s[r][k], acc);
            gi_s[r][gg] = acc;
        }
    }
    __syncthreads();

    // h' per (row, s=lane)
#pragma unroll
    for (int q = 0; q < 8; q++) {
        const int r = w * 8 + q;
        const float rr = 1.f / (1.f + expf(-(gi_s[r][lane] + bhh_s[lane])));
        const float zz = 1.f / (1.f + expf(-(gi_s[r][32 + lane] + bhh_s[32 + lane])));
        const float nn = tanhf(gi_s[r][64 + lane] + rr * bhh_s[64 + lane]);
        const float hv = (1.f - zz) * nn;
        h_s[r][lane] = hv;
        g_h[(r0 + r) * 32 + lane] = hv;
    }
    __syncthreads();

    // prep: thread (w,lane) computes Ai/Bj for rows w*8..w*8+7, m = lane
#pragma unroll 1
    for (int q = 0; q < 8; q++) {
        const int r = w * 8 + q;
        const float* wr = &w1_s[lane * 67];
        float hi = 0.f, hj = 0.f;
#pragma unroll
        for (int s = 0; s < 32; s++) {
            hi = fmaf(wr[s], h_s[r][s], hi);
            hj = fmaf(wr[32 + s], h_s[r][s], hj);
        }
        const float bi = b_s[r];
        g_Ai[(r0 + r) * 32 + lane] = hi + bi * wr[65] + b1_s[lane];
        g_Bj[(r0 + r) * 32 + lane] = hj + bi * wr[66];
        g_msum[(r0 + r) * 32 + lane] = 0.f;
    }
}

// ---------------------------------------------------------------------------
__global__ __launch_bounds__(128, 1)
void readout_kernel(const float* __restrict__ R1, const float* __restrict__ rb1,
                    const float* __restrict__ R2, const float* __restrict__ rb2,
                    const float* __restrict__ R3, const float* __restrict__ rb3,
                    float* __restrict__ out)
{
    __shared__ float r1_s[32 * 32];
    __shared__ float r2_s[32 * 32];
    __shared__ float r3_s[2 * 32];
    __shared__ float rb1_s[32], rb2_s[32];

    const int tid = threadIdx.x;
    for (int idx = tid; idx < 1024; idx += 128) {
        r1_s[idx] = R1[idx];
        r2_s[idx] = R2[idx];
    }
    if (tid < 64) r3_s[tid] = R3[tid];
    if (tid < 32) { rb1_s[tid] = rb1[tid]; rb2_s[tid] = rb2[tid]; }
    __syncthreads();

    const int i = blockIdx.x * 128 + tid;
    float hrow[32];
#pragma unroll
    for (int s = 0; s < 32; s++) hrow[s] = g_h[i * 32 + s];

    float a[32];
    for (int m = 0; m < 32; m++) {
        float acc = rb1_s[m];
#pragma unroll
        for (int k = 0; k < 32; k++) acc = fmaf(r1_s[m * 32 + k], hrow[k], acc);
        a[m] = fmaxf(acc, 0.f);
    }
    float c[32];
    for (int m = 0; m < 32; m++) {
        float acc = rb2_s[m];
#pragma unroll
        for (int k = 0; k < 32; k++) acc = fmaf(r2_s[m * 32 + k], a[k], acc);
        c[m] = fmaxf(acc, 0.f);
    }
#pragma unroll
    for (int o = 0; o < 2; o++) {
        float acc = rb3[o];
#pragma unroll
        for (int k = 0; k < 32; k++) acc = fmaf(r3_s[o * 32 + k], c[k], acc);
        acc = fmaxf(acc, 0.f);
        out[i * 2 + o] = 1.f / (1.f + expf(-acc));
    }
}

// ---------------------------------------------------------------------------
extern "C" void kernel_launch(void* const* d_in, const int* in_sizes, int n_in,
                              void* d_out, int out_size)
{
    const float* J   = (const float*)d_in[0];
    const float* b   = (const float*)d_in[1];
    const float* W1  = (const float*)d_in[2];
    const float* b1  = (const float*)d_in[3];
    const float* W2  = (const float*)d_in[4];
    const float* b2  = (const float*)d_in[5];
    const float* W3  = (const float*)d_in[6];
    const float* b3  = (const float*)d_in[7];
    const float* Wih = (const float*)d_in[8];
    const float* bih = (const float*)d_in[9];
    const float* bhh = (const float*)d_in[10];
    const float* R1  = (const float*)d_in[11];
    const float* rb1 = (const float*)d_in[12];
    const float* R2  = (const float*)d_in[13];
    const float* rb2 = (const float*)d_in[14];
    const float* R3  = (const float*)d_in[15];
    const float* rb3 = (const float*)d_in[16];
    float* out = (float*)d_out;

    init_kernel<<<128, 256>>>(W1, b, b1);
    for (int step = 0; step < 5; step++) {
        edge_kernel<<<dim3(32, 16), 128>>>(J, W1, W2, W3, b2, b3);
        gruprep_kernel<<<32, 128>>>(Wih, bih, bhh, W1, b, b1);
    }
    readout_kernel<<<8, 128>>>(R1, rb1, R2, rb2, R3, rb3, out);
}

// round 15
// speedup vs baseline: 1.5038x; 1.5038x over previous
#include <cuda_runtime.h>
#include <cuda_bf16.h>
#include <math.h>
#include <cstdint>

#define NN 1024
#define MV 32

// Scratch (allocation-free: __device__ globals)
__device__ float g_h[NN * MV];
__device__ float g_Ai[NN * MV];
__device__ float g_Bj[NN * MV];
__device__ float g_msum[NN * MV];

// ---------------- warp-MMA helpers (baseline PTX, sm_80+) ------------------
__device__ __forceinline__ void mma16816(float* d, const uint32_t* a,
                                         uint32_t b0, uint32_t b1)
{
    asm volatile("mma.sync.aligned.m16n8k16.row.col.f32.bf16.bf16.f32 "
                 "{%0,%1,%2,%3}, {%4,%5,%6,%7}, {%8,%9}, {%0,%1,%2,%3};"
                 : "+f"(d[0]), "+f"(d[1]), "+f"(d[2]), "+f"(d[3])
                 : "r"(a[0]), "r"(a[1]), "r"(a[2]), "r"(a[3]), "r"(b0), "r"(b1));
}
__device__ __forceinline__ uint32_t pack_bf(float a, float b)
{
    __nv_bfloat162 t = __floats2bfloat162_rn(a, b);   // .x=a (low), .y=b (high)
    return *reinterpret_cast<uint32_t*>(&t);
}
// split (a,b) -> hi plane bf16x2 + lo (residual) plane bf16x2, register-only
__device__ __forceinline__ void split2(float a, float b, uint32_t& hi, uint32_t& lo)
{
    hi = pack_bf(a, b);
    const float fa = __uint_as_float(hi << 16);
    const float fb = __uint_as_float(hi & 0xFFFF0000u);
    lo = pack_bf(a - fa, b - fb);
}

// ---------------------------------------------------------------------------
// init: h=0, msum=0, Ai = b[i]*wbi + b1, Bj = b[i]*wbj  (closed form at h=0)
// ---------------------------------------------------------------------------
__global__ __launch_bounds__(256, 1)
void init_kernel(const float* __restrict__ W1,
                 const float* __restrict__ b,
                 const float* __restrict__ b1)
{
    const int idx = blockIdx.x * 256 + threadIdx.x;     // 0..32767
    const int i = idx >> 5, m = idx & 31;
    const float bi = b[i];
    g_h[idx] = 0.f;
    g_msum[idx] = 0.f;
    g_Ai[idx] = bi * W1[m * 67 + 65] + b1[m];
    g_Bj[idx] = bi * W1[m * 67 + 66];
}

// ---------------------------------------------------------------------------
// Edge MLP: register-resident mma.sync pipeline (bf16 hi/lo 3-product).
// Grid (32 j-tiles, 32 i-chunks), block 128 (4 warps), 16 iterations of a
// 64-row chunk (2 i x 32 j; warp w owns rows w*16..w*16+15).
// x1 built directly into A-fragments; layer-2 D fragment == layer-3 A
// fragment layout -> zero ldmatrix, zero activation smem, zero hot-loop syncs.
// ---------------------------------------------------------------------------
__global__ __launch_bounds__(128)
void edge_kernel(const float* __restrict__ Jm,
                 const float* __restrict__ W1,
                 const float* __restrict__ W2,
                 const float* __restrict__ W3,
                 const float* __restrict__ b2,
                 const float* __restrict__ b3)
{
    __shared__ float j_s[1024];                   // [il][j]
    __shared__ float ai_s[1024];                  // [il][k]
    __shared__ alignas(8) uint32_t wfrag[2048];   // B-frags [plane][kt][nt][lane]{b0,b1}
    __shared__ float red_s[32 * 33];

    const int tid = threadIdx.x;
    const int lane = tid & 31, w = tid >> 5;
    const int j0 = blockIdx.x * 32, i0 = blockIdx.y * 32;
    const int g = lane >> 2, t4 = lane & 3;

    // ---- stage J (32x32), Ai (32x32) ----
    for (int idx = tid; idx < 1024; idx += 128) {
        j_s[idx] = Jm[(size_t)(i0 + (idx >> 5)) * NN + j0 + (idx & 31)];
        ai_s[idx] = g_Ai[(i0 + (idx >> 5)) * 32 + (idx & 31)];
    }
    // ---- precompute B fragments: planes 0=W2hi 1=W2lo 2=W3hi 3=W3lo ----
    for (int e = tid; e < 1024; e += 128) {
        const int ln = e & 31, q = e >> 5, nt = q & 3, q2 = q >> 2;
        const int kt = q2 & 1, plane = q2 >> 1;
        const int gg = ln >> 2, tt = ln & 3;
        const int n = nt * 8 + gg, k0 = kt * 16 + 2 * tt;
        const float* Wm = (plane < 2) ? W2 : W3;
        float v00 = Wm[n * 32 + k0],     v01 = Wm[n * 32 + k0 + 1];
        float v10 = Wm[n * 32 + k0 + 8], v11 = Wm[n * 32 + k0 + 9];
        if (plane & 1) {
            v00 -= __bfloat162float(__float2bfloat16_rn(v00));
            v01 -= __bfloat162float(__float2bfloat16_rn(v01));
            v10 -= __bfloat162float(__float2bfloat16_rn(v10));
            v11 -= __bfloat162float(__float2bfloat16_rn(v11));
        }
        wfrag[2 * e]     = pack_bf(v00, v01);
        wfrag[2 * e + 1] = pack_bf(v10, v11);
    }
    __syncthreads();

    // ---- per-thread loop-invariant hoists (registers) ----
    const int jloc = (w & 1) * 16 + g;            // this thread's first j row
    float2 wj2[4], bja[4], bjb[4];
#pragma unroll
    for (int f = 0; f < 4; f++) {
        const int k = f * 8 + 2 * t4;
        wj2[f].x = W1[k * 67 + 64];
        wj2[f].y = W1[(k + 1) * 67 + 64];
        bja[f] = *reinterpret_cast<const float2*>(&g_Bj[(size_t)(j0 + jloc) * 32 + k]);
        bjb[f] = *reinterpret_cast<const float2*>(&g_Bj[(size_t)(j0 + jloc + 8) * 32 + k]);
    }
    float b2c[8], b3c[8];
#pragma unroll
    for (int nt = 0; nt < 4; nt++) {
        b2c[2 * nt]     = b2[nt * 8 + 2 * t4];
        b2c[2 * nt + 1] = b2[nt * 8 + 2 * t4 + 1];
        b3c[2 * nt]     = b3[nt * 8 + 2 * t4];
        b3c[2 * nt + 1] = b3[nt * 8 + 2 * t4 + 1];
    }
    const uint2* wf = reinterpret_cast<const uint2*>(wfrag);
    const int ilw = w >> 1;

    float macc[16];
#pragma unroll
    for (int q = 0; q < 16; q++) macc[q] = 0.f;

#pragma unroll 1
    for (int it = 0; it < 16; it++) {
        const int il = it * 2 + ilw;
        const float Jv0 = j_s[il * 32 + jloc];
        const float Jv1 = j_s[il * 32 + jloc + 8];

        uint32_t ah[8], al[8];
        // ---- build x1 directly into A fragments ----
#pragma unroll
        for (int f = 0; f < 4; f++) {
            const float2 av = *reinterpret_cast<const float2*>(&ai_s[il * 32 + f * 8 + 2 * t4]);
            const float v00 = fmaxf(fmaf(Jv0, wj2[f].x, av.x + bja[f].x), 0.f);
            const float v01 = fmaxf(fmaf(Jv0, wj2[f].y, av.y + bja[f].y), 0.f);
            const float v10 = fmaxf(fmaf(Jv1, wj2[f].x, av.x + bjb[f].x), 0.f);
            const float v11 = fmaxf(fmaf(Jv1, wj2[f].y, av.y + bjb[f].y), 0.f);
            const int base = (f >> 1) * 4 + (f & 1) * 2;
            split2(v00, v01, ah[base],     al[base]);
            split2(v10, v11, ah[base + 1], al[base + 1]);
        }

        float d[16];
        // ================= layer 2 =================
#pragma unroll
        for (int q = 0; q < 16; q++) d[q] = 0.f;
#pragma unroll
        for (int kt = 0; kt < 2; kt++) {
#pragma unroll
            for (int nt = 0; nt < 4; nt++) {
                const uint2 bh = wf[((0 + kt) * 4 + nt) * 32 + lane];
                const uint2 bl = wf[((2 + kt) * 4 + nt) * 32 + lane];
                mma16816(d + 4 * nt, ah + 4 * kt, bh.x, bh.y);
                mma16816(d + 4 * nt, al + 4 * kt, bh.x, bh.y);
                mma16816(d + 4 * nt, ah + 4 * kt, bl.x, bl.y);
            }
        }
        // ---- epilogue: D frag -> layer-3 A frag, all in registers ----
#pragma unroll
        for (int nt = 0; nt < 4; nt++) {
            const float v00 = fmaxf(d[4 * nt + 0] + b2c[2 * nt],     0.f);
            const float v01 = fmaxf(d[4 * nt + 1] + b2c[2 * nt + 1], 0.f);
            const float v10 = fmaxf(d[4 * nt + 2] + b2c[2 * nt],     0.f);
            const float v11 = fmaxf(d[4 * nt + 3] + b2c[2 * nt + 1], 0.f);
            const int base = (nt >> 1) * 4 + (nt & 1) * 2;
            split2(v00, v01, ah[base],     al[base]);
            split2(v10, v11, ah[base + 1], al[base + 1]);
        }
        // ================= layer 3 =================
#pragma unroll
        for (int q = 0; q < 16; q++) d[q] = 0.f;
#pragma unroll
        for (int kt = 0; kt < 2; kt++) {
#pragma unroll
            for (int nt = 0; nt < 4; nt++) {
                const uint2 bh = wf[((4 + kt) * 4 + nt) * 32 + lane];
                const uint2 bl = wf[((6 + kt) * 4 + nt) * 32 + lane];
                mma16816(d + 4 * nt, ah + 4 * kt, bh.x, bh.y);
                mma16816(d + 4 * nt, al + 4 * kt, bh.x, bh.y);
                mma16816(d + 4 * nt, ah + 4 * kt, bl.x, bl.y);
            }
        }
#pragma unroll
        for (int nt = 0; nt < 4; nt++) {
            macc[4 * nt + 0] += fmaxf(d[4 * nt + 0] + b3c[2 * nt],     0.f);
            macc[4 * nt + 1] += fmaxf(d[4 * nt + 1] + b3c[2 * nt + 1], 0.f);
            macc[4 * nt + 2] += fmaxf(d[4 * nt + 2] + b3c[2 * nt],     0.f);
            macc[4 * nt + 3] += fmaxf(d[4 * nt + 3] + b3c[2 * nt + 1], 0.f);
        }
    }

    // ---- reduce i-partials (warps {0,2} and {1,3} share j ranges) ----
    const int rjA = (w & 1) * 16 + g;
    if (w < 2) {
#pragma unroll
        for (int nt = 0; nt < 4; nt++) {
            const int c0 = nt * 8 + 2 * t4;
            red_s[rjA * 33 + c0]           = macc[4 * nt + 0];
            red_s[rjA * 33 + c0 + 1]       = macc[4 * nt + 1];
            red_s[(rjA + 8) * 33 + c0]     = macc[4 * nt + 2];
            red_s[(rjA + 8) * 33 + c0 + 1] = macc[4 * nt + 3];
        }
    }
    __syncthreads();
    if (w >= 2) {
#pragma unroll
        for (int nt = 0; nt < 4; nt++) {
            const int c0 = nt * 8 + 2 * t4;
            red_s[rjA * 33 + c0]           += macc[4 * nt + 0];
            red_s[rjA * 33 + c0 + 1]       += macc[4 * nt + 1];
            red_s[(rjA + 8) * 33 + c0]     += macc[4 * nt + 2];
            red_s[(rjA + 8) * 33 + c0 + 1] += macc[4 * nt + 3];
        }
    }
    __syncthreads();
    {
        const int jj = tid >> 2, mq = (tid & 3) * 8;
        float* dst = g_msum + (size_t)(j0 + jj) * 32 + mq;
#pragma unroll
        for (int q = 0; q < 8; q++) atomicAdd(dst + q, red_s[jj * 33 + mq + q]);
    }
}

// ---------------------------------------------------------------------------
// Fused GRU + next-step prep. 64 blocks x 128 threads; block owns 16 rows.
// ---------------------------------------------------------------------------
__global__ __launch_bounds__(128, 1)
void gruprep_kernel(const float* __restrict__ Wih,
                    const float* __restrict__ bih,
                    const float* __restrict__ bhh,
                    const float* __restrict__ W1,
                    const float* __restrict__ b,
                    const float* __restrict__ b1)
{
    __shared__ float wih_s[96 * 65];
    __shared__ float w1_s[32 * 67];
    __shared__ float inp_s[16][65];
    __shared__ float gi_s[16][97];
    __shared__ float h_s[16][33];
    __shared__ float bih_s[96], bhh_s[96], b1_s[32], b_s[32];

    const int tid = threadIdx.x;
    const int r0 = blockIdx.x * 16;
    for (int idx = tid; idx < 96 * 64; idx += 128)
        wih_s[(idx >> 6) * 65 + (idx & 63)] = Wih[idx];
    for (int idx = tid; idx < 32 * 67; idx += 128) w1_s[idx] = W1[idx];
    if (tid < 96) { bih_s[tid] = bih[tid]; bhh_s[tid] = bhh[tid]; }
    if (tid < 32) { b1_s[tid] = b1[tid]; b_s[tid] = b[r0 + tid % 16 + (tid / 16) * 0]; }
    if (tid < 16) b_s[tid] = b[r0 + tid];
    for (int idx = tid; idx < 1024; idx += 128) {
        const int r = idx >> 6, k = idx & 63;
        inp_s[r][k] = (k < 32) ? g_h[(r0 + r) * 32 + k]
                               : g_msum[(r0 + r) * 32 + (k - 32)];
    }
    __syncthreads();

    const int w = tid >> 5, lane = tid & 31;

    // gi: warp w owns rows w*4..w*4+3; lane computes gates lane, +32, +64
#pragma unroll 1
    for (int q = 0; q < 4; q++) {
        const int r = w * 4 + q;
#pragma unroll
        for (int p = 0; p < 3; p++) {
            const int gg = lane + 32 * p;
            const float* wr = &wih_s[gg * 65];
            float acc = bih_s[gg];
#pragma unroll
            for (int k = 0; k < 64; k++) acc = fmaf(wr[k], inp_s[r][k], acc);
            gi_s[r][gg] = acc;
        }
    }
    __syncthreads();

    // h' per (row, s=lane)
#pragma unroll
    for (int q = 0; q < 4; q++) {
        const int r = w * 4 + q;
        const float rr = 1.f / (1.f + expf(-(gi_s[r][lane] + bhh_s[lane])));
        const float zz = 1.f / (1.f + expf(-(gi_s[r][32 + lane] + bhh_s[32 + lane])));
        const float nn = tanhf(gi_s[r][64 + lane] + rr * bhh_s[64 + lane]);
        const float hv = (1.f - zz) * nn;
        h_s[r][lane] = hv;
        g_h[(r0 + r) * 32 + lane] = hv;
    }
    __syncthreads();

    // prep: thread (w,lane) computes Ai/Bj for rows w*4..w*4+3, m = lane
#pragma unroll 1
    for (int q = 0; q < 4; q++) {
        const int r = w * 4 + q;
        const float* wr = &w1_s[lane * 67];
        float hi = 0.f, hj = 0.f;
#pragma unroll
        for (int s = 0; s < 32; s++) {
            hi = fmaf(wr[s], h_s[r][s], hi);
            hj = fmaf(wr[32 + s], h_s[r][s], hj);
        }
        const float bi = b_s[r];
        g_Ai[(r0 + r) * 32 + lane] = hi + bi * wr[65] + b1_s[lane];
        g_Bj[(r0 + r) * 32 + lane] = hj + bi * wr[66];
        g_msum[(r0 + r) * 32 + lane] = 0.f;
    }
}

// ---------------------------------------------------------------------------
__global__ __launch_bounds__(128, 1)
void readout_kernel(const float* __restrict__ R1, const float* __restrict__ rb1,
                    const float* __restrict__ R2, const float* __restrict__ rb2,
                    const float* __restrict__ R3, const float* __restrict__ rb3,
                    float* __restrict__ out)
{
    __shared__ float r1_s[32 * 32];
    __shared__ float r2_s[32 * 32];
    __shared__ float r3_s[2 * 32];
    __shared__ float rb1_s[32], rb2_s[32];

    const int tid = threadIdx.x;
    for (int idx = tid; idx < 1024; idx += 128) {
        r1_s[idx] = R1[idx];
        r2_s[idx] = R2[idx];
    }
    if (tid < 64) r3_s[tid] = R3[tid];
    if (tid < 32) { rb1_s[tid] = rb1[tid]; rb2_s[tid] = rb2[tid]; }
    __syncthreads();

    const int i = blockIdx.x * 128 + tid;
    float hrow[32];
#pragma unroll
    for (int s = 0; s < 32; s++) hrow[s] = g_h[i * 32 + s];

    float a[32];
    for (int m = 0; m < 32; m++) {
        float acc = rb1_s[m];
#pragma unroll
        for (int k = 0; k < 32; k++) acc = fmaf(r1_s[m * 32 + k], hrow[k], acc);
        a[m] = fmaxf(acc, 0.f);
    }
    float c[32];
    for (int m = 0; m < 32; m++) {
        float acc = rb2_s[m];
#pragma unroll
        for (int k = 0; k < 32; k++) acc = fmaf(r2_s[m * 32 + k], a[k], acc);
        c[m] = fmaxf(acc, 0.f);
    }
#pragma unroll
    for (int o = 0; o < 2; o++) {
        float acc = rb3[o];
#pragma unroll
        for (int k = 0; k < 32; k++) acc = fmaf(r3_s[o * 32 + k], c[k], acc);
        acc = fmaxf(acc, 0.f);
        out[i * 2 + o] = 1.f / (1.f + expf(-acc));
    }
}

// ---------------------------------------------------------------------------
extern "C" void kernel_launch(void* const* d_in, const int* in_sizes, int n_in,
                              void* d_out, int out_size)
{
    const float* J   = (const float*)d_in[0];
    const float* b   = (const float*)d_in[1];
    const float* W1  = (const float*)d_in[2];
    const float* b1  = (const float*)d_in[3];
    const float* W2  = (const float*)d_in[4];
    const float* b2  = (const float*)d_in[5];
    const float* W3  = (const float*)d_in[6];
    const float* b3  = (const float*)d_in[7];
    const float* Wih = (const float*)d_in[8];
    const float* bih = (const float*)d_in[9];
    const float* bhh = (const float*)d_in[10];
    const float* R1  = (const float*)d_in[11];
    const float* rb1 = (const float*)d_in[12];
    const float* R2  = (const float*)d_in[13];
    const float* rb2 = (const float*)d_in[14];
    const float* R3  = (const float*)d_in[15];
    const float* rb3 = (const float*)d_in[16];
    float* out = (float*)d_out;

    init_kernel<<<128, 256>>>(W1, b, b1);
    for (int step = 0; step < 5; step++) {
        edge_kernel<<<dim3(32, 32), 128>>>(J, W1, W2, W3, b2, b3);
        gruprep_kernel<<<64, 128>>>(Wih, bih, bhh, W1, b, b1);
    }
    readout_kernel<<<8, 128>>>(R1, rb1, R2, rb2, R3, rb3, out);
}

// round 16
// speedup vs baseline: 1.5754x; 1.0476x over previous
#include <cuda_runtime.h>
#include <cuda_bf16.h>
#include <math.h>
#include <cstdint>

#define NN 1024
#define MV 32

// Scratch (allocation-free: __device__ globals)
__device__ float g_h[NN * MV];
__device__ float g_Ai[NN * MV];
__device__ float g_Bj[NN * MV];
__device__ float g_msum[NN * MV];

// ---------------- warp-MMA helpers (baseline PTX, sm_80+) ------------------
__device__ __forceinline__ void mma16816(float* d, const uint32_t* a,
                                         uint32_t b0, uint32_t b1)
{
    asm volatile("mma.sync.aligned.m16n8k16.row.col.f32.bf16.bf16.f32 "
                 "{%0,%1,%2,%3}, {%4,%5,%6,%7}, {%8,%9}, {%0,%1,%2,%3};"
                 : "+f"(d[0]), "+f"(d[1]), "+f"(d[2]), "+f"(d[3])
                 : "r"(a[0]), "r"(a[1]), "r"(a[2]), "r"(a[3]), "r"(b0), "r"(b1));
}
__device__ __forceinline__ uint32_t pack_bf(float a, float b)
{
    __nv_bfloat162 t = __floats2bfloat162_rn(a, b);   // .x=a (low), .y=b (high)
    return *reinterpret_cast<uint32_t*>(&t);
}
// split (a,b) -> hi plane bf16x2 + lo (residual) plane bf16x2, register-only
__device__ __forceinline__ void split2(float a, float b, uint32_t& hi, uint32_t& lo)
{
    hi = pack_bf(a, b);
    const float fa = __uint_as_float(hi << 16);
    const float fb = __uint_as_float(hi & 0xFFFF0000u);
    lo = pack_bf(a - fa, b - fb);
}

// ---------------------------------------------------------------------------
// init: h=0, msum=0, Ai = b[i]*wbi + b1, Bj = b[i]*wbj  (closed form at h=0)
// ---------------------------------------------------------------------------
__global__ __launch_bounds__(256, 1)
void init_kernel(const float* __restrict__ W1,
                 const float* __restrict__ b,
                 const float* __restrict__ b1)
{
    const int idx = blockIdx.x * 256 + threadIdx.x;     // 0..32767
    const int i = idx >> 5, m = idx & 31;
    const float bi = b[i];
    g_h[idx] = 0.f;
    g_msum[idx] = 0.f;
    g_Ai[idx] = bi * W1[m * 67 + 65] + b1[m];
    g_Bj[idx] = bi * W1[m * 67 + 66];
}

// ---------------------------------------------------------------------------
// Edge MLP: register-resident mma.sync pipeline (bf16 hi/lo 3-product).
// Grid (32 j-tiles, 32 i-chunks), block 128 (4 warps), 16 iterations of a
// 64-row chunk. Hi-plane B fragments hoisted to registers (used 2x per
// product-triple); lo planes remain in smem. Zero hot-loop syncs.
// ---------------------------------------------------------------------------
__global__ __launch_bounds__(128)
void edge_kernel(const float* __restrict__ Jm,
                 const float* __restrict__ W1,
                 const float* __restrict__ W2,
                 const float* __restrict__ W3,
                 const float* __restrict__ b2,
                 const float* __restrict__ b3)
{
    __shared__ float j_s[1024];                   // [il][j]
    __shared__ float ai_s[1024];                  // [il][k]
    __shared__ alignas(8) uint32_t wfrag[2048];   // B-frags [plane][kt][nt][lane]{b0,b1}
    __shared__ float red_s[32 * 33];

    const int tid = threadIdx.x;
    const int lane = tid & 31, w = tid >> 5;
    const int j0 = blockIdx.x * 32, i0 = blockIdx.y * 32;
    const int g = lane >> 2, t4 = lane & 3;

    // ---- stage J (32x32), Ai (32x32) ----
    for (int idx = tid; idx < 1024; idx += 128) {
        j_s[idx] = Jm[(size_t)(i0 + (idx >> 5)) * NN + j0 + (idx & 31)];
        ai_s[idx] = g_Ai[(i0 + (idx >> 5)) * 32 + (idx & 31)];
    }
    // ---- precompute B fragments: planes 0=W2hi 1=W2lo 2=W3hi 3=W3lo ----
    for (int e = tid; e < 1024; e += 128) {
        const int ln = e & 31, q = e >> 5, nt = q & 3, q2 = q >> 2;
        const int kt = q2 & 1, plane = q2 >> 1;
        const int gg = ln >> 2, tt = ln & 3;
        const int n = nt * 8 + gg, k0 = kt * 16 + 2 * tt;
        const float* Wm = (plane < 2) ? W2 : W3;
        float v00 = Wm[n * 32 + k0],     v01 = Wm[n * 32 + k0 + 1];
        float v10 = Wm[n * 32 + k0 + 8], v11 = Wm[n * 32 + k0 + 9];
        if (plane & 1) {
            v00 -= __bfloat162float(__float2bfloat16_rn(v00));
            v01 -= __bfloat162float(__float2bfloat16_rn(v01));
            v10 -= __bfloat162float(__float2bfloat16_rn(v10));
            v11 -= __bfloat162float(__float2bfloat16_rn(v11));
        }
        wfrag[2 * e]     = pack_bf(v00, v01);
        wfrag[2 * e + 1] = pack_bf(v10, v11);
    }
    __syncthreads();

    const uint2* wf = reinterpret_cast<const uint2*>(wfrag);

    // ---- hoist HI-plane B fragments to registers (loop-invariant) ----
    // entry index: (plane*2 + kt)*4 + nt ; W2hi=plane0 -> 0..7, W3hi=plane2 -> 16..23
    uint2 w2h[8], w3h[8];
#pragma unroll
    for (int e = 0; e < 8; e++) {
        w2h[e] = wf[e * 32 + lane];
        w3h[e] = wf[(16 + e) * 32 + lane];
    }

    // ---- per-thread loop-invariant hoists ----
    const int jloc = (w & 1) * 16 + g;            // this thread's first j row
    float2 wj2[4], bja[4], bjb[4];
#pragma unroll
    for (int f = 0; f < 4; f++) {
        const int k = f * 8 + 2 * t4;
        wj2[f].x = W1[k * 67 + 64];
        wj2[f].y = W1[(k + 1) * 67 + 64];
        bja[f] = *reinterpret_cast<const float2*>(&g_Bj[(size_t)(j0 + jloc) * 32 + k]);
        bjb[f] = *reinterpret_cast<const float2*>(&g_Bj[(size_t)(j0 + jloc + 8) * 32 + k]);
    }
    float b2c[8], b3c[8];
#pragma unroll
    for (int nt = 0; nt < 4; nt++) {
        b2c[2 * nt]     = b2[nt * 8 + 2 * t4];
        b2c[2 * nt + 1] = b2[nt * 8 + 2 * t4 + 1];
        b3c[2 * nt]     = b3[nt * 8 + 2 * t4];
        b3c[2 * nt + 1] = b3[nt * 8 + 2 * t4 + 1];
    }
    const int ilw = w >> 1;

    float macc[16];
#pragma unroll
    for (int q = 0; q < 16; q++) macc[q] = 0.f;

#pragma unroll 1
    for (int it = 0; it < 16; it++) {
        const int il = it * 2 + ilw;
        const float Jv0 = j_s[il * 32 + jloc];
        const float Jv1 = j_s[il * 32 + jloc + 8];

        uint32_t ah[8], al[8];
        // ---- build x1 directly into A fragments ----
#pragma unroll
        for (int f = 0; f < 4; f++) {
            const float2 av = *reinterpret_cast<const float2*>(&ai_s[il * 32 + f * 8 + 2 * t4]);
            const float v00 = fmaxf(fmaf(Jv0, wj2[f].x, av.x + bja[f].x), 0.f);
            const float v01 = fmaxf(fmaf(Jv0, wj2[f].y, av.y + bja[f].y), 0.f);
            const float v10 = fmaxf(fmaf(Jv1, wj2[f].x, av.x + bjb[f].x), 0.f);
            const float v11 = fmaxf(fmaf(Jv1, wj2[f].y, av.y + bjb[f].y), 0.f);
            const int base = (f >> 1) * 4 + (f & 1) * 2;
            split2(v00, v01, ah[base],     al[base]);
            split2(v10, v11, ah[base + 1], al[base + 1]);
        }

        float d[16];
        // ================= layer 2 =================
#pragma unroll
        for (int q = 0; q < 16; q++) d[q] = 0.f;
#pragma unroll
        for (int kt = 0; kt < 2; kt++) {
#pragma unroll
            for (int nt = 0; nt < 4; nt++) {
                const uint2 bh = w2h[kt * 4 + nt];
                const uint2 bl = wf[((2 + kt) * 4 + nt) * 32 + lane];
                mma16816(d + 4 * nt, ah + 4 * kt, bh.x, bh.y);
                mma16816(d + 4 * nt, al + 4 * kt, bh.x, bh.y);
                mma16816(d + 4 * nt, ah + 4 * kt, bl.x, bl.y);
            }
        }
        // ---- epilogue: D frag -> layer-3 A frag, all in registers ----
#pragma unroll
        for (int nt = 0; nt < 4; nt++) {
            const float v00 = fmaxf(d[4 * nt + 0] + b2c[2 * nt],     0.f);
            const float v01 = fmaxf(d[4 * nt + 1] + b2c[2 * nt + 1], 0.f);
            const float v10 = fmaxf(d[4 * nt + 2] + b2c[2 * nt],     0.f);
            const float v11 = fmaxf(d[4 * nt + 3] + b2c[2 * nt + 1], 0.f);
            const int base = (nt >> 1) * 4 + (nt & 1) * 2;
            split2(v00, v01, ah[base],     al[base]);
            split2(v10, v11, ah[base + 1], al[base + 1]);
        }
        // ================= layer 3 =================
#pragma unroll
        for (int q = 0; q < 16; q++) d[q] = 0.f;
#pragma unroll
        for (int kt = 0; kt < 2; kt++) {
#pragma unroll
            for (int nt = 0; nt < 4; nt++) {
                const uint2 bh = w3h[kt * 4 + nt];
                const uint2 bl = wf[((6 + kt) * 4 + nt) * 32 + lane];
                mma16816(d + 4 * nt, ah + 4 * kt, bh.x, bh.y);
                mma16816(d + 4 * nt, al + 4 * kt, bh.x, bh.y);
                mma16816(d + 4 * nt, ah + 4 * kt, bl.x, bl.y);
            }
        }
#pragma unroll
        for (int nt = 0; nt < 4; nt++) {
            macc[4 * nt + 0] += fmaxf(d[4 * nt + 0] + b3c[2 * nt],     0.f);
            macc[4 * nt + 1] += fmaxf(d[4 * nt + 1] + b3c[2 * nt + 1], 0.f);
            macc[4 * nt + 2] += fmaxf(d[4 * nt + 2] + b3c[2 * nt],     0.f);
            macc[4 * nt + 3] += fmaxf(d[4 * nt + 3] + b3c[2 * nt + 1], 0.f);
        }
    }

    // ---- reduce i-partials (warps {0,2} and {1,3} share j ranges) ----
    const int rjA = (w & 1) * 16 + g;
    if (w < 2) {
#pragma unroll
        for (int nt = 0; nt < 4; nt++) {
            const int c0 = nt * 8 + 2 * t4;
            red_s[rjA * 33 + c0]           = macc[4 * nt + 0];
            red_s[rjA * 33 + c0 + 1]       = macc[4 * nt + 1];
            red_s[(rjA + 8) * 33 + c0]     = macc[4 * nt + 2];
            red_s[(rjA + 8) * 33 + c0 + 1] = macc[4 * nt + 3];
        }
    }
    __syncthreads();
    if (w >= 2) {
#pragma unroll
        for (int nt = 0; nt < 4; nt++) {
            const int c0 = nt * 8 + 2 * t4;
            red_s[rjA * 33 + c0]           += macc[4 * nt + 0];
            red_s[rjA * 33 + c0 + 1]       += macc[4 * nt + 1];
            red_s[(rjA + 8) * 33 + c0]     += macc[4 * nt + 2];
            red_s[(rjA + 8) * 33 + c0 + 1] += macc[4 * nt + 3];
        }
    }
    __syncthreads();
    {
        const int jj = tid >> 2, mq = (tid & 3) * 8;
        float* dst = g_msum + (size_t)(j0 + jj) * 32 + mq;
#pragma unroll
        for (int q = 0; q < 8; q++) atomicAdd(dst + q, red_s[jj * 33 + mq + q]);
    }
}

// ---------------------------------------------------------------------------
// Fused GRU + next-step prep. 128 blocks x 128 threads; block owns 8 rows.
// ---------------------------------------------------------------------------
__global__ __launch_bounds__(128, 1)
void gruprep_kernel(const float* __restrict__ Wih,
                    const float* __restrict__ bih,
                    const float* __restrict__ bhh,
                    const float* __restrict__ W1,
                    const float* __restrict__ b,
                    const float* __restrict__ b1)
{
    __shared__ float wih_s[96 * 65];
    __shared__ float w1_s[32 * 67];
    __shared__ float inp_s[8][65];
    __shared__ float gi_s[8][97];
    __shared__ float h_s[8][33];
    __shared__ float bih_s[96], bhh_s[96], b1_s[32], b_s[8];

    const int tid = threadIdx.x;
    const int r0 = blockIdx.x * 8;
    for (int idx = tid; idx < 96 * 64; idx += 128)
        wih_s[(idx >> 6) * 65 + (idx & 63)] = Wih[idx];
    for (int idx = tid; idx < 32 * 67; idx += 128) w1_s[idx] = W1[idx];
    if (tid < 96) { bih_s[tid] = bih[tid]; bhh_s[tid] = bhh[tid]; }
    if (tid < 32) b1_s[tid] = b1[tid];
    if (tid < 8) b_s[tid] = b[r0 + tid];
    for (int idx = tid; idx < 512; idx += 128) {
        const int r = idx >> 6, k = idx & 63;
        inp_s[r][k] = (k < 32) ? g_h[(r0 + r) * 32 + k]
                               : g_msum[(r0 + r) * 32 + (k - 32)];
    }
    __syncthreads();

    const int w = tid >> 5, lane = tid & 31;

    // gi: warp w owns rows w*2, w*2+1; lane computes gates lane, +32, +64
#pragma unroll
    for (int q = 0; q < 2; q++) {
        const int r = w * 2 + q;
#pragma unroll
        for (int p = 0; p < 3; p++) {
            const int gg = lane + 32 * p;
            const float* wr = &wih_s[gg * 65];
            float acc = bih_s[gg];
#pragma unroll
            for (int k = 0; k < 64; k++) acc = fmaf(wr[k], inp_s[r][k], acc);
            gi_s[r][gg] = acc;
        }
    }
    __syncthreads();

    // h' per (row, s=lane)
#pragma unroll
    for (int q = 0; q < 2; q++) {
        const int r = w * 2 + q;
        const float rr = 1.f / (1.f + expf(-(gi_s[r][lane] + bhh_s[lane])));
        const float zz = 1.f / (1.f + expf(-(gi_s[r][32 + lane] + bhh_s[32 + lane])));
        const float nn = tanhf(gi_s[r][64 + lane] + rr * bhh_s[64 + lane]);
        const float hv = (1.f - zz) * nn;
        h_s[r][lane] = hv;
        g_h[(r0 + r) * 32 + lane] = hv;
    }
    __syncthreads();

    // prep: thread (w,lane) computes Ai/Bj for rows w*2..w*2+1, m = lane
#pragma unroll
    for (int q = 0; q < 2; q++) {
        const int r = w * 2 + q;
        const float* wr = &w1_s[lane * 67];
        float hi = 0.f, hj = 0.f;
#pragma unroll
        for (int s = 0; s < 32; s++) {
            hi = fmaf(wr[s], h_s[r][s], hi);
            hj = fmaf(wr[32 + s], h_s[r][s], hj);
        }
        const float bi = b_s[r];
        g_Ai[(r0 + r) * 32 + lane] = hi + bi * wr[65] + b1_s[lane];
        g_Bj[(r0 + r) * 32 + lane] = hj + bi * wr[66];
        g_msum[(r0 + r) * 32 + lane] = 0.f;
    }
}

// ---------------------------------------------------------------------------
__global__ __launch_bounds__(128, 1)
void readout_kernel(const float* __restrict__ R1, const float* __restrict__ rb1,
                    const float* __restrict__ R2, const float* __restrict__ rb2,
                    const float* __restrict__ R3, const float* __restrict__ rb3,
                    float* __restrict__ out)
{
    __shared__ float r1_s[32 * 32];
    __shared__ float r2_s[32 * 32];
    __shared__ float r3_s[2 * 32];
    __shared__ float rb1_s[32], rb2_s[32];

    const int tid = threadIdx.x;
    for (int idx = tid; idx < 1024; idx += 128) {
        r1_s[idx] = R1[idx];
        r2_s[idx] = R2[idx];
    }
    if (tid < 64) r3_s[tid] = R3[tid];
    if (tid < 32) { rb1_s[tid] = rb1[tid]; rb2_s[tid] = rb2[tid]; }
    __syncthreads();

    const int i = blockIdx.x * 128 + tid;
    float hrow[32];
#pragma unroll
    for (int s = 0; s < 32; s++) hrow[s] = g_h[i * 32 + s];

    float a[32];
    for (int m = 0; m < 32; m++) {
        float acc = rb1_s[m];
#pragma unroll
        for (int k = 0; k < 32; k++) acc = fmaf(r1_s[m * 32 + k], hrow[k], acc);
        a[m] = fmaxf(acc, 0.f);
    }
    float c[32];
    for (int m = 0; m < 32; m++) {
        float acc = rb2_s[m];
#pragma unroll
        for (int k = 0; k < 32; k++) acc = fmaf(r2_s[m * 32 + k], a[k], acc);
        c[m] = fmaxf(acc, 0.f);
    }
#pragma unroll
    for (int o = 0; o < 2; o++) {
        float acc = rb3[o];
#pragma unroll
        for (int k = 0; k < 32; k++) acc = fmaf(r3_s[o * 32 + k], c[k], acc);
        acc = fmaxf(acc, 0.f);
        out[i * 2 + o] = 1.f / (1.f + expf(-acc));
    }
}

// ---------------------------------------------------------------------------
extern "C" void kernel_launch(void* const* d_in, const int* in_sizes, int n_in,
                              void* d_out, int out_size)
{
    const float* J   = (const float*)d_in[0];
    const float* b   = (const float*)d_in[1];
    const float* W1  = (const float*)d_in[2];
    const float* b1  = (const float*)d_in[3];
    const float* W2  = (const float*)d_in[4];
    const float* b2  = (const float*)d_in[5];
    const float* W3  = (const float*)d_in[6];
    const float* b3  = (const float*)d_in[7];
    const float* Wih = (const float*)d_in[8];
    const float* bih = (const float*)d_in[9];
    const float* bhh = (const float*)d_in[10];
    const float* R1  = (const float*)d_in[11];
    const float* rb1 = (const float*)d_in[12];
    const float* R2  = (const float*)d_in[13];
    const float* rb2 = (const float*)d_in[14];
    const float* R3  = (const float*)d_in[15];
    const float* rb3 = (const float*)d_in[16];
    float* out = (float*)d_out;

    init_kernel<<<128, 256>>>(W1, b, b1);
    for (int step = 0; step < 5; step++) {
        edge_kernel<<<dim3(32, 32), 128>>>(J, W1, W2, W3, b2, b3);
        gruprep_kernel<<<128, 128>>>(Wih, bih, bhh, W1, b, b1);
    }
    readout_kernel<<<8, 128>>>(R1, rb1, R2, rb2, R3, rb3, out);
}